// round 8
// baseline (speedup 1.0000x reference)
#include <cuda_runtime.h>
#include <cuda_bf16.h>

// Model: x[n,t,:] = [features[n,0..11], AVG[t]]  (T=120, F=13)
// h1 = LSTM(H=30)(x);  out = LSTM(H=1)(h1)
// One warp per TWO sequences (A,B). Lane u<30 owns hidden unit u of LSTM1 and
// holds its 4 gate rows packed as f32x2 pairs (i,f)/(g,o) — weights are shared
// by both sequences, so seq B costs only ~25 extra state registers but doubles
// the independent dependency chains per warp (fills the activation-latency
// bubbles that capped issue-active at 57%).
// Lane 30 carries W_ih2 in the same slots -> the shfl/FFMA2 k-loop also
// produces LSTM2's input dots for both sequences.

#define TT   120
#define HH   30
#define FEAT 12

typedef unsigned long long u64;

__constant__ float AVG_c[TT] = {
    0.0256f,0.0823f,0.1157f,0.1315f,0.1366f,0.1369f,0.1347f,0.1308f,0.1259f,0.1205f,
    0.1146f,0.1086f,0.1028f,0.0970f,0.0913f,0.0858f,0.0805f,0.0756f,0.0708f,0.0664f,
    0.0623f,0.0584f,0.0549f,0.0515f,0.0485f,0.0456f,0.0429f,0.0404f,0.0381f,0.0360f,
    0.0340f,0.0321f,0.0304f,0.0287f,0.0272f,0.0258f,0.0245f,0.0233f,0.0222f,0.0211f,
    0.0201f,0.0191f,0.0182f,0.0173f,0.0165f,0.0158f,0.0150f,0.0143f,0.0137f,0.0130f,
    0.0125f,0.0119f,0.0114f,0.0108f,0.0104f,0.0099f,0.0095f,0.0091f,0.0087f,0.0083f,
    0.0080f,0.0077f,0.0074f,0.0071f,0.0068f,0.0065f,0.0062f,0.0060f,0.0058f,0.0055f,
    0.0053f,0.0050f,0.0049f,0.0047f,0.0045f,0.0044f,0.0042f,0.0040f,0.0039f,0.0038f,
    0.0036f,0.0034f,0.0033f,0.0032f,0.0031f,0.0030f,0.0029f,0.0028f,0.0027f,0.0026f,
    0.0025f,0.0024f,0.0023f,0.0022f,0.0021f,0.0021f,0.0020f,0.0019f,0.0018f,0.0018f,
    0.0017f,0.0017f,0.0016f,0.0016f,0.0015f,0.0015f,0.0014f,0.0014f,0.0013f,0.0013f,
    0.0013f,0.0012f,0.0012f,0.0011f,0.0011f,0.0011f,0.0010f,0.0010f,0.0010f,0.0009f
};

// ---- packed f32x2 helpers (Blackwell) ----
__device__ __forceinline__ u64 pack2(float lo, float hi) {
    u64 d; asm("mov.b64 %0, {%1, %2};" : "=l"(d) : "f"(lo), "f"(hi)); return d;
}
__device__ __forceinline__ u64 pack2_dup(float x) {
    u64 d; asm("mov.b64 %0, {%1, %1};" : "=l"(d) : "f"(x)); return d;
}
__device__ __forceinline__ void unpack2(u64 v, float& lo, float& hi) {
    asm("mov.b64 {%0, %1}, %2;" : "=f"(lo), "=f"(hi) : "l"(v));
}
__device__ __forceinline__ u64 fma2(u64 a, u64 b, u64 c) {
    u64 d; asm("fma.rn.f32x2 %0, %1, %2, %3;" : "=l"(d) : "l"(a), "l"(b), "l"(c)); return d;
}

__device__ __forceinline__ float sigmoid_f(float x) {
    float e = __expf(-x);
    return __fdividef(1.0f, 1.0f + e);
}
__device__ __forceinline__ float tanh_f(float x) {
    float e = __expf(2.0f * x);
    return 1.0f - __fdividef(2.0f, 1.0f + e);
}

__global__ __launch_bounds__(64, 5)
void lstm_trace_kernel(const float* __restrict__ features,
                       const float* __restrict__ w_ih1,   // [120,13]
                       const float* __restrict__ w_hh1,   // [120,30]
                       const float* __restrict__ b1,      // [120]
                       const float* __restrict__ w_ih2,   // [4,30]
                       const float* __restrict__ w_hh2,   // [4,1]
                       const float* __restrict__ b2,      // [4]
                       float* __restrict__ out,           // [N,120]
                       int N)
{
    const int warp_gid = (blockIdx.x * blockDim.x + threadIdx.x) >> 5;
    const int lane     = threadIdx.x & 31;
    const int seqA = warp_gid * 2;
    const int seqB = seqA + 1;
    if (seqA >= N) return;
    const bool hasB = (seqB < N);
    const int seqBs = hasB ? seqB : seqA;   // safe index for loads

    const float* featA = features + seqA  * FEAT;
    const float* featB = features + seqBs * FEAT;

    // ---- shared per-lane packed weights ----
    u64 wif[HH], wgo[HH];
    u64 w12_if = 0ull, w12_go = 0ull;
    u64 baseA_if = 0ull, baseA_go = 0ull;
    u64 baseB_if = 0ull, baseB_go = 0ull;

    if (lane < HH) {
        const float* ri = w_hh1 + (0 * HH + lane) * HH;
        const float* rf = w_hh1 + (1 * HH + lane) * HH;
        const float* rg = w_hh1 + (2 * HH + lane) * HH;
        const float* ro = w_hh1 + (3 * HH + lane) * HH;
        #pragma unroll
        for (int k = 0; k < HH; k++) {
            wif[k] = pack2(ri[k], rf[k]);
            wgo[k] = pack2(rg[k], ro[k]);
        }
        const float* pi = w_ih1 + (0 * HH + lane) * (FEAT + 1);
        const float* pf = w_ih1 + (1 * HH + lane) * (FEAT + 1);
        const float* pg = w_ih1 + (2 * HH + lane) * (FEAT + 1);
        const float* po = w_ih1 + (3 * HH + lane) * (FEAT + 1);
        float bi = b1[0 * HH + lane];
        float bf = b1[1 * HH + lane];
        float bg = b1[2 * HH + lane];
        float bo = b1[3 * HH + lane];
        float ai = bi, af = bf, ag = bg, ao = bo;
        float ci = bi, cf = bf, cg = bg, co = bo;
        #pragma unroll
        for (int d = 0; d < FEAT; d++) {
            float fa = featA[d], fb = featB[d];
            ai = fmaf(fa, pi[d], ai);  ci = fmaf(fb, pi[d], ci);
            af = fmaf(fa, pf[d], af);  cf = fmaf(fb, pf[d], cf);
            ag = fmaf(fa, pg[d], ag);  cg = fmaf(fb, pg[d], cg);
            ao = fmaf(fa, po[d], ao);  co = fmaf(fb, po[d], co);
        }
        baseA_if = pack2(ai, af);  baseA_go = pack2(ag, ao);
        baseB_if = pack2(ci, cf);  baseB_go = pack2(cg, co);
        w12_if = pack2(pi[FEAT], pf[FEAT]);
        w12_go = pack2(pg[FEAT], po[FEAT]);
    } else if (lane == HH) {
        #pragma unroll
        for (int k = 0; k < HH; k++) {
            wif[k] = pack2(w_ih2[0 * HH + k], w_ih2[1 * HH + k]);
            wgo[k] = pack2(w_ih2[2 * HH + k], w_ih2[3 * HH + k]);
        }
    } else {
        #pragma unroll
        for (int k = 0; k < HH; k++) { wif[k] = 0ull; wgo[k] = 0ull; }
    }

    // LSTM2 scalar params (uniform, all lanes)
    const float wh2_0 = w_hh2[0], wh2_1 = w_hh2[1], wh2_2 = w_hh2[2], wh2_3 = w_hh2[3];
    const float b2_0 = b2[0], b2_1 = b2[1], b2_2 = b2[2], b2_3 = b2[3];

    float h1a = 0.f, c1a = 0.f, h1b = 0.f, c1b = 0.f;
    float h2a = 0.f, c2a = 0.f, h2b = 0.f, c2b = 0.f;
    float* outA = out + seqA  * TT;
    float* outB = out + seqBs * TT;

    #pragma unroll 1
    for (int t = 0; t < TT; t++) {
        const u64 at2 = pack2_dup(AVG_c[t]);
        u64 aifA = fma2(at2, w12_if, baseA_if);
        u64 agoA = fma2(at2, w12_go, baseA_go);
        u64 aifB = fma2(at2, w12_if, baseB_if);
        u64 agoB = fma2(at2, w12_go, baseB_go);
        #pragma unroll
        for (int k = 0; k < HH; k++) {
            u64 ha = pack2_dup(__shfl_sync(0xffffffffu, h1a, k));
            aifA = fma2(ha, wif[k], aifA);
            agoA = fma2(ha, wgo[k], agoA);
            u64 hb = pack2_dup(__shfl_sync(0xffffffffu, h1b, k));
            aifB = fma2(hb, wif[k], aifB);
            agoB = fma2(hb, wgo[k], agoB);
        }
        float giA, gfA, ggA, goA, giB, gfB, ggB, goB;
        unpack2(aifA, giA, gfA);  unpack2(agoA, ggA, goA);
        unpack2(aifB, giB, gfB);  unpack2(agoB, ggB, goB);

        // ---- LSTM2 step (t-1): lane 30's dots of h1[t-1] ----
        if (t > 0) {
            float aiA = giA + fmaf(wh2_0, h2a, b2_0);
            float afA = gfA + fmaf(wh2_1, h2a, b2_1);
            float agA = ggA + fmaf(wh2_2, h2a, b2_2);
            float aoA = goA + fmaf(wh2_3, h2a, b2_3);
            c2a = sigmoid_f(afA) * c2a + sigmoid_f(aiA) * tanh_f(agA);
            h2a = sigmoid_f(aoA) * tanh_f(c2a);

            float aiB = giB + fmaf(wh2_0, h2b, b2_0);
            float afB = gfB + fmaf(wh2_1, h2b, b2_1);
            float agB = ggB + fmaf(wh2_2, h2b, b2_2);
            float aoB = goB + fmaf(wh2_3, h2b, b2_3);
            c2b = sigmoid_f(afB) * c2b + sigmoid_f(aiB) * tanh_f(agB);
            h2b = sigmoid_f(aoB) * tanh_f(c2b);

            if (lane == HH) {
                outA[t - 1] = h2a;
                if (hasB) outB[t - 1] = h2b;
            }
        }

        // ---- LSTM1 updates (lanes < 30 hold valid data; others never read) ----
        float siA = sigmoid_f(giA), sfA = sigmoid_f(gfA);
        float sgA = tanh_f(ggA),    soA = sigmoid_f(goA);
        c1a = sfA * c1a + siA * sgA;
        h1a = soA * tanh_f(c1a);

        float siB = sigmoid_f(giB), sfB = sigmoid_f(gfB);
        float sgB = tanh_f(ggB),    soB = sigmoid_f(goB);
        c1b = sfB * c1b + siB * sgB;
        h1b = soB * tanh_f(c1b);
    }

    // ---- epilogue: LSTM2 step 119 using h1[119] ----
    {
        u64 aifA = 0ull, agoA = 0ull, aifB = 0ull, agoB = 0ull;
        #pragma unroll
        for (int k = 0; k < HH; k++) {
            u64 ha = pack2_dup(__shfl_sync(0xffffffffu, h1a, k));
            aifA = fma2(ha, wif[k], aifA);
            agoA = fma2(ha, wgo[k], agoA);
            u64 hb = pack2_dup(__shfl_sync(0xffffffffu, h1b, k));
            aifB = fma2(hb, wif[k], aifB);
            agoB = fma2(hb, wgo[k], agoB);
        }
        float giA, gfA, ggA, goA, giB, gfB, ggB, goB;
        unpack2(aifA, giA, gfA);  unpack2(agoA, ggA, goA);
        unpack2(aifB, giB, gfB);  unpack2(agoB, ggB, goB);

        float aiA = giA + fmaf(wh2_0, h2a, b2_0);
        float afA = gfA + fmaf(wh2_1, h2a, b2_1);
        float agA = ggA + fmaf(wh2_2, h2a, b2_2);
        float aoA = goA + fmaf(wh2_3, h2a, b2_3);
        c2a = sigmoid_f(afA) * c2a + sigmoid_f(aiA) * tanh_f(agA);
        h2a = sigmoid_f(aoA) * tanh_f(c2a);

        float aiB = giB + fmaf(wh2_0, h2b, b2_0);
        float afB = gfB + fmaf(wh2_1, h2b, b2_1);
        float agB = ggB + fmaf(wh2_2, h2b, b2_2);
        float aoB = goB + fmaf(wh2_3, h2b, b2_3);
        c2b = sigmoid_f(afB) * c2b + sigmoid_f(aiB) * tanh_f(agB);
        h2b = sigmoid_f(aoB) * tanh_f(c2b);

        if (lane == HH) {
            outA[TT - 1] = h2a;
            if (hasB) outB[TT - 1] = h2b;
        }
    }
}

extern "C" void kernel_launch(void* const* d_in, const int* in_sizes, int n_in,
                              void* d_out, int out_size) {
    const float* features = (const float*)d_in[0];
    const float* w_ih1    = (const float*)d_in[1];
    const float* w_hh1    = (const float*)d_in[2];
    const float* b1       = (const float*)d_in[3];
    const float* w_ih2    = (const float*)d_in[4];
    const float* w_hh2    = (const float*)d_in[5];
    const float* b2       = (const float*)d_in[6];
    float* out = (float*)d_out;

    const int N = in_sizes[0] / FEAT;               // 32768
    const int n_warps = (N + 1) / 2;                // 2 sequences per warp
    const int threads = 64;                         // 2 warps/block -> 5 CTAs/SM
    const int blocks  = (n_warps * 32 + threads - 1) / threads;

    lstm_trace_kernel<<<blocks, threads>>>(features, w_ih1, w_hh1, b1,
                                           w_ih2, w_hh2, b2, out, N);
}

// round 12
// speedup vs baseline: 1.1418x; 1.1418x over previous
#include <cuda_runtime.h>
#include <cuda_bf16.h>

// Model: x[n,t,:] = [features[n,0..11], AVG[t]]  (T=120, F=13)
// h1 = LSTM(H=30)(x);  out = LSTM(H=1)(h1)
//
// Warp-per-sequence (proven-fit register config), smem h-broadcast:
//   lane u<30 owns hidden unit u; its 4 gate rows of W_hh1 live in registers
//   k-pair-packed: wXX[m] = {W[u][2m], W[u][2m+1]} (u64 f32x2).
//   Per step: each lane STS's its h into a per-warp 32-float buffer; the
//   k-loop is 15 broadcast LDS.64 pair-loads feeding fma.rn.f32x2 (60/step).
//   No shuffles, no dup-MOVs. Halves summed once per gate.
//   Lane 30 carries W_ih2 in the same slots -> LSTM2 input dot rides the same
//   loop, one step behind. Lane 31 idle (zero weights).

#define TT   120
#define HH   30
#define FEAT 12
#define NPAIR 15

typedef unsigned long long u64;

__constant__ float AVG_c[TT] = {
    0.0256f,0.0823f,0.1157f,0.1315f,0.1366f,0.1369f,0.1347f,0.1308f,0.1259f,0.1205f,
    0.1146f,0.1086f,0.1028f,0.0970f,0.0913f,0.0858f,0.0805f,0.0756f,0.0708f,0.0664f,
    0.0623f,0.0584f,0.0549f,0.0515f,0.0485f,0.0456f,0.0429f,0.0404f,0.0381f,0.0360f,
    0.0340f,0.0321f,0.0304f,0.0287f,0.0272f,0.0258f,0.0245f,0.0233f,0.0222f,0.0211f,
    0.0201f,0.0191f,0.0182f,0.0173f,0.0165f,0.0158f,0.0150f,0.0143f,0.0137f,0.0130f,
    0.0125f,0.0119f,0.0114f,0.0108f,0.0104f,0.0099f,0.0095f,0.0091f,0.0087f,0.0083f,
    0.0080f,0.0077f,0.0074f,0.0071f,0.0068f,0.0065f,0.0062f,0.0060f,0.0058f,0.0055f,
    0.0053f,0.0050f,0.0049f,0.0047f,0.0045f,0.0044f,0.0042f,0.0040f,0.0039f,0.0038f,
    0.0036f,0.0034f,0.0033f,0.0032f,0.0031f,0.0030f,0.0029f,0.0028f,0.0027f,0.0026f,
    0.0025f,0.0024f,0.0023f,0.0022f,0.0021f,0.0021f,0.0020f,0.0019f,0.0018f,0.0018f,
    0.0017f,0.0017f,0.0016f,0.0016f,0.0015f,0.0015f,0.0014f,0.0014f,0.0013f,0.0013f,
    0.0013f,0.0012f,0.0012f,0.0011f,0.0011f,0.0011f,0.0010f,0.0010f,0.0010f,0.0009f
};

// ---- packed f32x2 helpers (Blackwell) ----
__device__ __forceinline__ u64 pack2(float lo, float hi) {
    u64 d; asm("mov.b64 %0, {%1, %2};" : "=l"(d) : "f"(lo), "f"(hi)); return d;
}
__device__ __forceinline__ void unpack2(u64 v, float& lo, float& hi) {
    asm("mov.b64 {%0, %1}, %2;" : "=f"(lo), "=f"(hi) : "l"(v));
}
__device__ __forceinline__ u64 fma2(u64 a, u64 b, u64 c) {
    u64 d; asm("fma.rn.f32x2 %0, %1, %2, %3;" : "=l"(d) : "l"(a), "l"(b), "l"(c)); return d;
}

__device__ __forceinline__ float sigmoid_f(float x) {
    float e = __expf(-x);
    return __fdividef(1.0f, 1.0f + e);
}
__device__ __forceinline__ float tanh_f(float x) {
    float e = __expf(2.0f * x);
    return 1.0f - __fdividef(2.0f, 1.0f + e);
}

__global__ __launch_bounds__(128, 3)
void lstm_trace_kernel(const float* __restrict__ features,
                       const float* __restrict__ w_ih1,   // [120,13]
                       const float* __restrict__ w_hh1,   // [120,30]
                       const float* __restrict__ b1,      // [120]
                       const float* __restrict__ w_ih2,   // [4,30]
                       const float* __restrict__ w_hh2,   // [4,1]
                       const float* __restrict__ b2,      // [4]
                       float* __restrict__ out,           // [N,120]
                       int N)
{
    __shared__ __align__(16) float hbuf[4][32];   // per-warp h broadcast buffer

    const int warp_id  = (blockIdx.x * blockDim.x + threadIdx.x) >> 5;
    const int lane     = threadIdx.x & 31;
    const int wslot    = (threadIdx.x >> 5) & 3;
    if (warp_id >= N) return;

    const float* feat = features + warp_id * FEAT;
    float* hrow = &hbuf[wslot][0];

    // ---- per-lane k-pair-packed weights ----
    u64 wi[NPAIR], wf[NPAIR], wg[NPAIR], wo[NPAIR];
    float base_i = 0.f, base_f = 0.f, base_g = 0.f, base_o = 0.f;
    float w12_i = 0.f, w12_f = 0.f, w12_g = 0.f, w12_o = 0.f;

    if (lane < HH) {
        const float* ri = w_hh1 + (0 * HH + lane) * HH;
        const float* rf = w_hh1 + (1 * HH + lane) * HH;
        const float* rg = w_hh1 + (2 * HH + lane) * HH;
        const float* ro = w_hh1 + (3 * HH + lane) * HH;
        #pragma unroll
        for (int m = 0; m < NPAIR; m++) {
            wi[m] = pack2(ri[2 * m], ri[2 * m + 1]);
            wf[m] = pack2(rf[2 * m], rf[2 * m + 1]);
            wg[m] = pack2(rg[2 * m], rg[2 * m + 1]);
            wo[m] = pack2(ro[2 * m], ro[2 * m + 1]);
        }
        const float* pi = w_ih1 + (0 * HH + lane) * (FEAT + 1);
        const float* pf = w_ih1 + (1 * HH + lane) * (FEAT + 1);
        const float* pg = w_ih1 + (2 * HH + lane) * (FEAT + 1);
        const float* po = w_ih1 + (3 * HH + lane) * (FEAT + 1);
        base_i = b1[0 * HH + lane];
        base_f = b1[1 * HH + lane];
        base_g = b1[2 * HH + lane];
        base_o = b1[3 * HH + lane];
        #pragma unroll
        for (int d = 0; d < FEAT; d++) {
            float fd = feat[d];
            base_i = fmaf(fd, pi[d], base_i);
            base_f = fmaf(fd, pf[d], base_f);
            base_g = fmaf(fd, pg[d], base_g);
            base_o = fmaf(fd, po[d], base_o);
        }
        w12_i = pi[FEAT]; w12_f = pf[FEAT]; w12_g = pg[FEAT]; w12_o = po[FEAT];
    } else if (lane == HH) {
        // LSTM2 input weights ride in the same register slots
        #pragma unroll
        for (int m = 0; m < NPAIR; m++) {
            wi[m] = pack2(w_ih2[0 * HH + 2 * m], w_ih2[0 * HH + 2 * m + 1]);
            wf[m] = pack2(w_ih2[1 * HH + 2 * m], w_ih2[1 * HH + 2 * m + 1]);
            wg[m] = pack2(w_ih2[2 * HH + 2 * m], w_ih2[2 * HH + 2 * m + 1]);
            wo[m] = pack2(w_ih2[3 * HH + 2 * m], w_ih2[3 * HH + 2 * m + 1]);
        }
    } else {
        #pragma unroll
        for (int m = 0; m < NPAIR; m++) { wi[m] = wf[m] = wg[m] = wo[m] = 0ull; }
    }

    // LSTM2 scalar params (uniform)
    const float wh2_0 = w_hh2[0], wh2_1 = w_hh2[1], wh2_2 = w_hh2[2], wh2_3 = w_hh2[3];
    const float b2_0 = b2[0], b2_1 = b2[1], b2_2 = b2[2], b2_3 = b2[3];

    // init h buffer to zeros
    hrow[lane] = 0.f;
    __syncwarp();

    float c1 = 0.f;              // lane u: LSTM1 cell state of unit u
    float h2 = 0.f, c2 = 0.f;    // valid in lane 30 only
    float* outp = out + warp_id * TT;

    #pragma unroll 1
    for (int t = 0; t < TT; t++) {
        const float at = AVG_c[t];
        u64 ai = pack2(fmaf(at, w12_i, base_i), 0.f);
        u64 af = pack2(fmaf(at, w12_f, base_f), 0.f);
        u64 ag = pack2(fmaf(at, w12_g, base_g), 0.f);
        u64 ao = pack2(fmaf(at, w12_o, base_o), 0.f);
        #pragma unroll
        for (int m = 0; m < NPAIR; m++) {
            const u64 hp = *reinterpret_cast<const u64*>(&hrow[2 * m]);  // broadcast LDS.64
            ai = fma2(hp, wi[m], ai);
            af = fma2(hp, wf[m], af);
            ag = fma2(hp, wg[m], ag);
            ao = fma2(hp, wo[m], ao);
        }
        float gi, gf, gg, go, xi, xf, xg, xo;
        unpack2(ai, gi, xi); gi += xi;
        unpack2(af, gf, xf); gf += xf;
        unpack2(ag, gg, xg); gg += xg;
        unpack2(ao, go, xo); go += xo;

        // ---- LSTM2 step (t-1): lane 30's gi..go = W_ih2 · h1[t-1] ----
        if (t > 0) {
            float a2i = gi + fmaf(wh2_0, h2, b2_0);
            float a2f = gf + fmaf(wh2_1, h2, b2_1);
            float a2g = gg + fmaf(wh2_2, h2, b2_2);
            float a2o = go + fmaf(wh2_3, h2, b2_3);
            c2 = sigmoid_f(a2f) * c2 + sigmoid_f(a2i) * tanh_f(a2g);
            h2 = sigmoid_f(a2o) * tanh_f(c2);
            if (lane == HH) outp[t - 1] = h2;
        }

        // ---- LSTM1 update (lanes < 30 meaningful; others write junk to unread slots) ----
        float si = sigmoid_f(gi);
        float sf = sigmoid_f(gf);
        float sg = tanh_f(gg);
        float so = sigmoid_f(go);
        c1 = sf * c1 + si * sg;
        float hnew = so * tanh_f(c1);

        __syncwarp();            // everyone done reading h[t-1]
        hrow[lane] = hnew;       // publish h[t] (lanes 30/31 write unread slots 30/31)
        __syncwarp();            // h[t] visible before next iteration's loads
    }

    // ---- epilogue: LSTM2 step 119 using h1[119] ----
    {
        u64 ai = 0ull, af = 0ull, ag = 0ull, ao = 0ull;
        #pragma unroll
        for (int m = 0; m < NPAIR; m++) {
            const u64 hp = *reinterpret_cast<const u64*>(&hrow[2 * m]);
            ai = fma2(hp, wi[m], ai);
            af = fma2(hp, wf[m], af);
            ag = fma2(hp, wg[m], ag);
            ao = fma2(hp, wo[m], ao);
        }
        float gi, gf, gg, go, xi, xf, xg, xo;
        unpack2(ai, gi, xi); gi += xi;
        unpack2(af, gf, xf); gf += xf;
        unpack2(ag, gg, xg); gg += xg;
        unpack2(ao, go, xo); go += xo;

        float a2i = gi + fmaf(wh2_0, h2, b2_0);
        float a2f = gf + fmaf(wh2_1, h2, b2_1);
        float a2g = gg + fmaf(wh2_2, h2, b2_2);
        float a2o = go + fmaf(wh2_3, h2, b2_3);
        c2 = sigmoid_f(a2f) * c2 + sigmoid_f(a2i) * tanh_f(a2g);
        h2 = sigmoid_f(a2o) * tanh_f(c2);
        if (lane == HH) outp[TT - 1] = h2;
    }
}

extern "C" void kernel_launch(void* const* d_in, const int* in_sizes, int n_in,
                              void* d_out, int out_size) {
    const float* features = (const float*)d_in[0];
    const float* w_ih1    = (const float*)d_in[1];
    const float* w_hh1    = (const float*)d_in[2];
    const float* b1       = (const float*)d_in[3];
    const float* w_ih2    = (const float*)d_in[4];
    const float* w_hh2    = (const float*)d_in[5];
    const float* b2       = (const float*)d_in[6];
    float* out = (float*)d_out;

    const int N = in_sizes[0] / FEAT;           // 32768
    const int threads = 128;                    // 4 warps/block, 3 CTAs/SM
    const int blocks  = (N * 32 + threads - 1) / threads;

    lstm_trace_kernel<<<blocks, threads>>>(features, w_ih1, w_hh1, b1,
                                           w_ih2, w_hh2, b2, out, N);
}

// round 13
// speedup vs baseline: 1.3408x; 1.1743x over previous
#include <cuda_runtime.h>
#include <cuda_bf16.h>

// Model: x[n,t,:] = [features[n,0..11], AVG[t]]  (T=120, F=13)
// h1 = LSTM(H=30)(x);  out = LSTM(H=1)(h1)
//
// Warp-per-sequence, smem h-broadcast (double-buffered), UNIFIED activation:
//   lane u<30 owns LSTM1 unit u (gate rows k-pair-packed f32x2 in registers);
//   lane 30 owns LSTM2 entirely: its matvec slot holds W_ih2 (input dot), and
//   per-lane constants wq/bq (zero on lanes!=30) fold the LSTM2 recurrent
//   term into the SAME activation block that lanes<30 use for LSTM1 —
//   gx += fmaf(wq, hself, bq) is exactly gx+0 for LSTM1 lanes. Lane 30's
//   c1/hself registers are c2/h2. One syncwarp per step (double buffer).

#define TT   120
#define HH   30
#define FEAT 12
#define NPAIR 15

typedef unsigned long long u64;

__constant__ float AVG_c[TT] = {
    0.0256f,0.0823f,0.1157f,0.1315f,0.1366f,0.1369f,0.1347f,0.1308f,0.1259f,0.1205f,
    0.1146f,0.1086f,0.1028f,0.0970f,0.0913f,0.0858f,0.0805f,0.0756f,0.0708f,0.0664f,
    0.0623f,0.0584f,0.0549f,0.0515f,0.0485f,0.0456f,0.0429f,0.0404f,0.0381f,0.0360f,
    0.0340f,0.0321f,0.0304f,0.0287f,0.0272f,0.0258f,0.0245f,0.0233f,0.0222f,0.0211f,
    0.0201f,0.0191f,0.0182f,0.0173f,0.0165f,0.0158f,0.0150f,0.0143f,0.0137f,0.0130f,
    0.0125f,0.0119f,0.0114f,0.0108f,0.0104f,0.0099f,0.0095f,0.0091f,0.0087f,0.0083f,
    0.0080f,0.0077f,0.0074f,0.0071f,0.0068f,0.0065f,0.0062f,0.0060f,0.0058f,0.0055f,
    0.0053f,0.0050f,0.0049f,0.0047f,0.0045f,0.0044f,0.0042f,0.0040f,0.0039f,0.0038f,
    0.0036f,0.0034f,0.0033f,0.0032f,0.0031f,0.0030f,0.0029f,0.0028f,0.0027f,0.0026f,
    0.0025f,0.0024f,0.0023f,0.0022f,0.0021f,0.0021f,0.0020f,0.0019f,0.0018f,0.0018f,
    0.0017f,0.0017f,0.0016f,0.0016f,0.0015f,0.0015f,0.0014f,0.0014f,0.0013f,0.0013f,
    0.0013f,0.0012f,0.0012f,0.0011f,0.0011f,0.0011f,0.0010f,0.0010f,0.0010f,0.0009f
};

// ---- packed f32x2 helpers (Blackwell) ----
__device__ __forceinline__ u64 pack2(float lo, float hi) {
    u64 d; asm("mov.b64 %0, {%1, %2};" : "=l"(d) : "f"(lo), "f"(hi)); return d;
}
__device__ __forceinline__ void unpack2(u64 v, float& lo, float& hi) {
    asm("mov.b64 {%0, %1}, %2;" : "=f"(lo), "=f"(hi) : "l"(v));
}
__device__ __forceinline__ u64 fma2(u64 a, u64 b, u64 c) {
    u64 d; asm("fma.rn.f32x2 %0, %1, %2, %3;" : "=l"(d) : "l"(a), "l"(b), "l"(c)); return d;
}

__device__ __forceinline__ float sigmoid_f(float x) {
    float e = __expf(-x);
    return __fdividef(1.0f, 1.0f + e);
}
__device__ __forceinline__ float tanh_f(float x) {
    float e = __expf(2.0f * x);
    return 1.0f - __fdividef(2.0f, 1.0f + e);
}

__global__ __launch_bounds__(128, 3)
void lstm_trace_kernel(const float* __restrict__ features,
                       const float* __restrict__ w_ih1,   // [120,13]
                       const float* __restrict__ w_hh1,   // [120,30]
                       const float* __restrict__ b1,      // [120]
                       const float* __restrict__ w_ih2,   // [4,30]
                       const float* __restrict__ w_hh2,   // [4,1]
                       const float* __restrict__ b2,      // [4]
                       float* __restrict__ out,           // [N,120]
                       int N)
{
    __shared__ __align__(16) float hbuf[4][64];   // per-warp double-buffered h row

    const int warp_id  = (blockIdx.x * blockDim.x + threadIdx.x) >> 5;
    const int lane     = threadIdx.x & 31;
    const int wslot    = (threadIdx.x >> 5) & 3;
    if (warp_id >= N) return;

    const float* feat = features + warp_id * FEAT;
    float* hrow = &hbuf[wslot][0];

    // ---- per-lane k-pair-packed weights ----
    u64 wi[NPAIR], wf[NPAIR], wg[NPAIR], wo[NPAIR];
    float base_i = 0.f, base_f = 0.f, base_g = 0.f, base_o = 0.f;
    float w12_i = 0.f, w12_f = 0.f, w12_g = 0.f, w12_o = 0.f;
    // unified-activation adjustment constants (nonzero only on lane 30)
    float wq_i = 0.f, wq_f = 0.f, wq_g = 0.f, wq_o = 0.f;
    float bq_i = 0.f, bq_f = 0.f, bq_g = 0.f, bq_o = 0.f;

    if (lane < HH) {
        const float* ri = w_hh1 + (0 * HH + lane) * HH;
        const float* rf = w_hh1 + (1 * HH + lane) * HH;
        const float* rg = w_hh1 + (2 * HH + lane) * HH;
        const float* ro = w_hh1 + (3 * HH + lane) * HH;
        #pragma unroll
        for (int m = 0; m < NPAIR; m++) {
            wi[m] = pack2(ri[2 * m], ri[2 * m + 1]);
            wf[m] = pack2(rf[2 * m], rf[2 * m + 1]);
            wg[m] = pack2(rg[2 * m], rg[2 * m + 1]);
            wo[m] = pack2(ro[2 * m], ro[2 * m + 1]);
        }
        const float* pi = w_ih1 + (0 * HH + lane) * (FEAT + 1);
        const float* pf = w_ih1 + (1 * HH + lane) * (FEAT + 1);
        const float* pg = w_ih1 + (2 * HH + lane) * (FEAT + 1);
        const float* po = w_ih1 + (3 * HH + lane) * (FEAT + 1);
        base_i = b1[0 * HH + lane];
        base_f = b1[1 * HH + lane];
        base_g = b1[2 * HH + lane];
        base_o = b1[3 * HH + lane];
        #pragma unroll
        for (int d = 0; d < FEAT; d++) {
            float fd = feat[d];
            base_i = fmaf(fd, pi[d], base_i);
            base_f = fmaf(fd, pf[d], base_f);
            base_g = fmaf(fd, pg[d], base_g);
            base_o = fmaf(fd, po[d], base_o);
        }
        w12_i = pi[FEAT]; w12_f = pf[FEAT]; w12_g = pg[FEAT]; w12_o = po[FEAT];
    } else if (lane == HH) {
        // LSTM2: input weights in the matvec slots, recurrent/bias in wq/bq
        #pragma unroll
        for (int m = 0; m < NPAIR; m++) {
            wi[m] = pack2(w_ih2[0 * HH + 2 * m], w_ih2[0 * HH + 2 * m + 1]);
            wf[m] = pack2(w_ih2[1 * HH + 2 * m], w_ih2[1 * HH + 2 * m + 1]);
            wg[m] = pack2(w_ih2[2 * HH + 2 * m], w_ih2[2 * HH + 2 * m + 1]);
            wo[m] = pack2(w_ih2[3 * HH + 2 * m], w_ih2[3 * HH + 2 * m + 1]);
        }
        wq_i = w_hh2[0]; wq_f = w_hh2[1]; wq_g = w_hh2[2]; wq_o = w_hh2[3];
        bq_i = b2[0];    bq_f = b2[1];    bq_g = b2[2];    bq_o = b2[3];
    } else {
        #pragma unroll
        for (int m = 0; m < NPAIR; m++) { wi[m] = wf[m] = wg[m] = wo[m] = 0ull; }
    }

    // zero the t=0 read buffer
    hrow[lane] = 0.f;
    __syncwarp();

    float c1 = 0.f;       // lane u<30: LSTM1 cell u; lane 30: c2
    float hself = 0.f;    // lane u<30: h1[u] (also published); lane 30: h2
    float* outp = out + warp_id * TT;

    #pragma unroll 1
    for (int t = 0; t < TT; t++) {
        const int roff = (t & 1) << 5;      // read buffer offset
        const int woff = roff ^ 32;         // write buffer offset
        const float at = AVG_c[t];

        u64 ai = pack2(fmaf(at, w12_i, base_i), 0.f);
        u64 af = pack2(fmaf(at, w12_f, base_f), 0.f);
        u64 ag = pack2(fmaf(at, w12_g, base_g), 0.f);
        u64 ao = pack2(fmaf(at, w12_o, base_o), 0.f);
        #pragma unroll
        for (int m = 0; m < NPAIR; m++) {
            const u64 hp = *reinterpret_cast<const u64*>(&hrow[roff + 2 * m]);  // broadcast LDS.64
            ai = fma2(hp, wi[m], ai);
            af = fma2(hp, wf[m], af);
            ag = fma2(hp, wg[m], ag);
            ao = fma2(hp, wo[m], ao);
        }
        float gi, gf, gg, go, xi, xf, xg, xo;
        unpack2(ai, gi, xi); gi += xi;
        unpack2(af, gf, xf); gf += xf;
        unpack2(ag, gg, xg); gg += xg;
        unpack2(ao, go, xo); go += xo;

        // unified adjustment: exact +0 on lanes<30; LSTM2 recurrent+bias on lane 30
        gi += fmaf(wq_i, hself, bq_i);
        gf += fmaf(wq_f, hself, bq_f);
        gg += fmaf(wq_g, hself, bq_g);
        go += fmaf(wq_o, hself, bq_o);

        // unified activation block (LSTM1 for lanes<30, LSTM2 for lane 30)
        float si = sigmoid_f(gi);
        float sf = sigmoid_f(gf);
        float sg = tanh_f(gg);
        float so = sigmoid_f(go);
        float cn = sf * c1 + si * sg;
        float hn = so * tanh_f(cn);

        // lane 30's t=0 update is bogus (LSTM2's first real step is t=1) -> reset
        if (t == 0 && lane == HH) { cn = 0.f; hn = 0.f; }
        c1 = cn;

        // store h2[t-1] (lane 30 pipeline is one step behind)
        if (t > 0 && lane == HH) outp[t - 1] = hn;

        hself = hn;
        hrow[woff + lane] = hn;   // lanes 30/31 write unread slots
        __syncwarp();
    }

    // ---- epilogue: LSTM2 step 119 using h1[119] (read buffer: offset 0) ----
    {
        u64 ai = 0ull, af = 0ull, ag = 0ull, ao = 0ull;
        #pragma unroll
        for (int m = 0; m < NPAIR; m++) {
            const u64 hp = *reinterpret_cast<const u64*>(&hrow[2 * m]);
            ai = fma2(hp, wi[m], ai);
            af = fma2(hp, wf[m], af);
            ag = fma2(hp, wg[m], ag);
            ao = fma2(hp, wo[m], ao);
        }
        float gi, gf, gg, go, xi, xf, xg, xo;
        unpack2(ai, gi, xi); gi += xi;
        unpack2(af, gf, xf); gf += xf;
        unpack2(ag, gg, xg); gg += xg;
        unpack2(ao, go, xo); go += xo;

        gi += fmaf(wq_i, hself, bq_i);
        gf += fmaf(wq_f, hself, bq_f);
        gg += fmaf(wq_g, hself, bq_g);
        go += fmaf(wq_o, hself, bq_o);

        float cn = sigmoid_f(gf) * c1 + sigmoid_f(gi) * tanh_f(gg);
        float hn = sigmoid_f(go) * tanh_f(cn);
        if (lane == HH) outp[TT - 1] = hn;
    }
}

extern "C" void kernel_launch(void* const* d_in, const int* in_sizes, int n_in,
                              void* d_out, int out_size) {
    const float* features = (const float*)d_in[0];
    const float* w_ih1    = (const float*)d_in[1];
    const float* w_hh1    = (const float*)d_in[2];
    const float* b1       = (const float*)d_in[3];
    const float* w_ih2    = (const float*)d_in[4];
    const float* w_hh2    = (const float*)d_in[5];
    const float* b2       = (const float*)d_in[6];
    float* out = (float*)d_out;

    const int N = in_sizes[0] / FEAT;           // 32768
    const int threads = 128;                    // 4 warps/block, 3 CTAs/SM
    const int blocks  = (N * 32 + threads - 1) / threads;

    lstm_trace_kernel<<<blocks, threads>>>(features, w_ih1, w_hh1, b1,
                                           w_ih2, w_hh2, b2, out, N);
}